// round 17
// baseline (speedup 1.0000x reference)
#include <cuda_runtime.h>
#include <cuda_bf16.h>
#include <cstdint>

#define NBATCH 8192
#define SETS   8
#define GRID   (NBATCH/SETS)
#define TPB    1024
#define NLAT   16

#define SA 136            // halfword stride for A1/W2/W3 [.][k] bf16 arrays
#define PLANE_A  34816    // 128*136*2 bytes
#define PLANE_W2 34816
#define PLANE_W3 8704     // 32*136*2
#define PLANE_X  6144     // 128*24*2

// ---------------- shared memory layout (bytes) ----------------
#define O_W2B 0           // W2 as B: [n=128][k=136] bf16, hi+lo planes (69632)
#define O_W3B 69632       // W3 as B: [n=32][k=136] bf16, hi+lo planes (17408)
#define O_A1  87040       // A: [m=128][k=136] bf16, hi+lo planes (69632)
#define O_ZP  156672      // Zpart[4][32][132] f32 = 67584 (dedicated, no alias)
#define O_WP  224256      // fspool weights f32 [32][128] (16384)  -- wait, too big
// NOTE: Zpart is [4][32][132] floats = 4*4224*4 = 67584 bytes. Recompute layout:
#undef O_ZP
#undef O_WP
#define O_ZP  156672      // 67584 -> ends 224256 ... exceeds budget with WP after.
// Use compact Zpart WITHOUT alias by keeping 4 slices but sharing with nothing:
// Total needed: 156672 + 67584 + 16384 + 12288 + 768 = 253696 > 227KB. Too big.
// => keep Zpart aliasing A1 is NOT needed if we shrink: store Z partials in
//    2 slices instead of 4 (pairs of wn combine via one extra register add).
//    Zpart2[2][32][132] = 33792 bytes.
#define O_ZP2 156672      // Zpart2[2][32][132] f32 (33792) -> ends 190464
#define O_WP  190464      // fspool weights f32 [32][128] (16384) -> 206848
#define O_W1B 206848      // [W1T|b1] bf16 [128][24] hi+lo planes (12288) -> 219136
#define O_B2  219136      // 512
#define O_B3  219648      // 128
#define O_PL  219776      // 128
#define SMEM_BYTES 219904

__device__ __forceinline__ uint32_t cvta_smem(const void* p) {
    uint32_t a;
    asm("{ .reg .u64 t; cvta.to.shared.u64 t, %1; cvt.u32.u64 %0, t; }" : "=r"(a) : "l"(p));
    return a;
}
// pack (lo element = a, hi element = b) with ONE cvt instruction
__device__ __forceinline__ uint32_t cvt2(float hi_elem, float lo_elem) {
    uint32_t r;
    asm("cvt.rn.bf16x2.f32 %0, %1, %2;" : "=r"(r) : "f"(hi_elem), "f"(lo_elem));
    return r;
}

#define LDSM4(R0,R1,R2,R3,ADDR) \
    asm volatile("ldmatrix.sync.aligned.m8n8.x4.shared.b16 {%0,%1,%2,%3}, [%4];" \
        : "=r"(R0),"=r"(R1),"=r"(R2),"=r"(R3) : "r"(ADDR) : "memory")

#define MMA(C,A,B) \
    asm volatile("mma.sync.aligned.m16n8k16.row.col.f32.bf16.bf16.f32 " \
        "{%0,%1,%2,%3}, {%4,%5,%6,%7}, {%8,%9}, {%0,%1,%2,%3};" \
        : "+f"((C)[0]),"+f"((C)[1]),"+f"((C)[2]),"+f"((C)[3]) \
        : "r"((A)[0]),"r"((A)[1]),"r"((A)[2]),"r"((A)[3]), "r"((B)[0]),"r"((B)[1]))

__global__ __launch_bounds__(TPB, 1)
void enc_kernel(const float* __restrict__ x,  const float* __restrict__ W1,
                const float* __restrict__ b1, const float* __restrict__ W2,
                const float* __restrict__ b2, const float* __restrict__ W3,
                const float* __restrict__ b3, const float* __restrict__ pwm,
                const float* __restrict__ eps, float* __restrict__ out)
{
    extern __shared__ __align__(1024) char smem[];
    const uint32_t sb = cvta_smem(smem);
    const int tid = threadIdx.x;
    const int wid = tid >> 5, lane = tid & 31;
    const int g = lane >> 2, t4 = lane & 3;
    const int l8 = lane & 7, mi = lane >> 3;

    __nv_bfloat16* sW2B = (__nv_bfloat16*)(smem + O_W2B);
    __nv_bfloat16* sW3B = (__nv_bfloat16*)(smem + O_W3B);
    float* sWp = (float*)(smem + O_WP);

    // ---------- stage invariant weights ----------
    {
        #pragma unroll 4
        for (int r = 0; r < 16; r++) {
            int i = tid + r * TPB;               // i = j*128 + n
            float v = W2[i];
            __nv_bfloat16 hi = __float2bfloat16_rn(v);
            __nv_bfloat16 lo = __float2bfloat16_rn(v - __bfloat162float(hi));
            int j = i >> 7, n = i & 127;
            sW2B[n*SA + j] = hi;
            sW2B[PLANE_W2/2 + n*SA + j] = lo;
        }
        #pragma unroll
        for (int r = 0; r < 4; r++) {
            int i = tid + r * TPB;               // i = k*32 + c
            float v = W3[i];
            __nv_bfloat16 hi = __float2bfloat16_rn(v);
            __nv_bfloat16 lo = __float2bfloat16_rn(v - __bfloat162float(hi));
            int k = i >> 5, c = i & 31;
            sW3B[c*SA + k] = hi;
            sW3B[PLANE_W3/2 + c*SA + k] = lo;
        }
        // W1B: row j, cols 0..3 = W1[f][j], col 4 = b1[j], rest 0.
        if (tid < 128) {
            int j = tid;
            uint32_t* wh = (uint32_t*)(smem + O_W1B) + j*12;
            uint32_t* wl = (uint32_t*)(smem + O_W1B + PLANE_X) + j*12;
            #pragma unroll
            for (int q = 0; q < 12; q++) { wh[q] = 0u; wl[q] = 0u; }
            float w0 = W1[j], w1 = W1[128 + j], w2_ = W1[256 + j], w3_ = W1[384 + j];
            float bb = b1[j];
            uint32_t p01 = cvt2(w1, w0);
            uint32_t p23 = cvt2(w3_, w2_);
            uint32_t pb  = cvt2(0.0f, bb);
            wh[0] = p01; wh[1] = p23; wh[2] = pb;
            wl[0] = cvt2(w1 - __uint_as_float(p01 & 0xFFFF0000u),
                         w0 - __uint_as_float(p01 << 16));
            wl[1] = cvt2(w3_ - __uint_as_float(p23 & 0xFFFF0000u),
                         w2_ - __uint_as_float(p23 << 16));
            wl[2] = cvt2(0.0f, bb - __uint_as_float(pb << 16));
        }
        if (tid >= 160 && tid < 192) ((float4*)(smem + O_B2))[tid-160] = ((const float4*)b2)[tid-160];
        if (tid >= 192 && tid < 200) ((float4*)(smem + O_B3))[tid-192] = ((const float4*)b3)[tid-192];
        #pragma unroll
        for (int r = 0; r < 4; r++) {
            int i = tid + r * TPB;
            int c = i >> 7, pp = i & 127;
            float pos = (float)pp / 127.0f * 20.0f;
            int idx = (int)pos; if (idx > 20) idx = 20;
            float frac = pos - (float)idx;
            int idx2 = idx + 1; if (idx2 > 20) idx2 = 20;
            sWp[i] = (1.0f - frac) * pwm[c*21 + idx] + frac * pwm[c*21 + idx2];
        }
    }
    __syncthreads();

    const int wm = wid >> 2, wn = wid & 3;       // 8 x 4 warp grid
    const int m0 = wm * 16, n0 = wn * 32;

    // ldmatrix per-lane geometry (verified passing since R11)
    const int aRow = (mi & 1) * 8 + l8;
    const int aCol = (mi >> 1) * 8;
    const int bRow = ((mi >> 1) & 1) * 8 + l8;
    const int bCol = (mi & 1) * 8;

    for (int s = 0; s < SETS; s++) {
        const int bset = blockIdx.x * SETS + s;

        // ---------- layer 1 via mma: X fragments built directly from global ----------
        {
            uint32_t xfh[4], xfl[4];
            xfh[2] = 0u; xfh[3] = 0u; xfl[2] = 0u; xfl[3] = 0u;
            if (t4 < 2) {
                const float2* xg = (const float2*)(x + (size_t)bset * 512);
                float2 v0 = xg[(m0 + g) * 2 + t4];        // row m0+g, cols {2t4, 2t4+1}
                float2 v1 = xg[(m0 + g + 8) * 2 + t4];    // row m0+g+8
                uint32_t p0 = cvt2(v0.y, v0.x);
                uint32_t p1 = cvt2(v1.y, v1.x);
                xfh[0] = p0;
                xfh[1] = p1;
                xfl[0] = cvt2(v0.y - __uint_as_float(p0 & 0xFFFF0000u),
                              v0.x - __uint_as_float(p0 << 16));
                xfl[1] = cvt2(v1.y - __uint_as_float(p1 & 0xFFFF0000u),
                              v1.x - __uint_as_float(p1 << 16));
            } else if (t4 == 2) {
                xfh[0] = cvt2(0.0f, 1.0f);   // col 4 = bias column of ones
                xfh[1] = xfh[0];
                xfl[0] = 0u; xfl[1] = 0u;
            } else {
                xfh[0] = 0u; xfh[1] = 0u; xfl[0] = 0u; xfl[1] = 0u;
            }

            uint32_t w1h[4][2], w1l[4][2];
            #pragma unroll
            for (int np = 0; np < 2; np++) {
                uint32_t addrh = sb + O_W1B + (uint32_t)((n0 + np*16 + bRow)*24 + bCol)*2;
                uint32_t r0,r1,r2,r3;
                LDSM4(r0,r1,r2,r3, addrh);
                w1h[2*np][0]=r0; w1h[2*np][1]=r1; w1h[2*np+1][0]=r2; w1h[2*np+1][1]=r3;
                LDSM4(r0,r1,r2,r3, addrh + PLANE_X);
                w1l[2*np][0]=r0; w1l[2*np][1]=r1; w1l[2*np+1][0]=r2; w1l[2*np+1][1]=r3;
            }
            float c1[4][4];
            #pragma unroll
            for (int j = 0; j < 4; j++)
                #pragma unroll
                for (int r = 0; r < 4; r++) c1[j][r] = 0.0f;
            #pragma unroll
            for (int nf = 0; nf < 4; nf++) {
                MMA(c1[nf], xfh, w1h[nf]);
                MMA(c1[nf], xfh, w1l[nf]);
                MMA(c1[nf], xfl, w1h[nf]);
            }
            uint32_t* a1h = (uint32_t*)(smem + O_A1);
            uint32_t* a1l = (uint32_t*)(smem + O_A1 + PLANE_A);
            #pragma unroll
            for (int nf = 0; nf < 4; nf++)
                #pragma unroll
                for (int h = 0; h < 2; h++) {
                    float v0 = fmaxf(c1[nf][2*h],   0.0f);
                    float v1 = fmaxf(c1[nf][2*h+1], 0.0f);
                    uint32_t ph = cvt2(v1, v0);
                    int m = m0 + g + 8*h;
                    int w = m*(SA/2) + (n0 >> 1) + 4*nf + t4;
                    a1h[w] = ph;
                    a1l[w] = cvt2(v1 - __uint_as_float(ph & 0xFFFF0000u),
                                  v0 - __uint_as_float(ph << 16));
                }
        }
        __syncthreads();   // B1: A1 visible

        // ---------- layer 2: C[16x32] per warp via mma.sync, 8 k-steps ----------
        float cacc[4][4];
        #pragma unroll
        for (int j = 0; j < 4; j++)
            #pragma unroll
            for (int r = 0; r < 4; r++) cacc[j][r] = 0.0f;
        {
            uint32_t aAddr[2], bAddr[2][2];
            #pragma unroll
            for (int pl = 0; pl < 2; pl++) {
                aAddr[pl] = sb + O_A1 + pl*PLANE_A + (uint32_t)((m0 + aRow)*SA + aCol)*2;
                #pragma unroll
                for (int np = 0; np < 2; np++)
                    bAddr[pl][np] = sb + O_W2B + pl*PLANE_W2
                                  + (uint32_t)((n0 + np*16 + bRow)*SA + bCol)*2;
            }
            #pragma unroll
            for (int kk = 0; kk < 8; kk++) {
                uint32_t af[2][4];
                #pragma unroll
                for (int pl = 0; pl < 2; pl++)
                    LDSM4(af[pl][0], af[pl][1], af[pl][2], af[pl][3], aAddr[pl] + kk*32);
                uint32_t bfr[2][4][2];
                #pragma unroll
                for (int pl = 0; pl < 2; pl++)
                    #pragma unroll
                    for (int np = 0; np < 2; np++) {
                        uint32_t r0,r1,r2,r3;
                        LDSM4(r0,r1,r2,r3, bAddr[pl][np] + kk*32);
                        bfr[pl][2*np][0]=r0; bfr[pl][2*np][1]=r1;
                        bfr[pl][2*np+1][0]=r2; bfr[pl][2*np+1][1]=r3;
                    }
                #pragma unroll
                for (int nf = 0; nf < 4; nf++) {
                    MMA(cacc[nf], af[0], bfr[0][nf]);   // hi*hi
                    MMA(cacc[nf], af[0], bfr[1][nf]);   // hi*lo
                    MMA(cacc[nf], af[1], bfr[0][nf]);   // lo*hi
                }
            }
        }

        // ---------- epilogue in registers: bias + relu + hi/lo split ----------
        uint32_t Ah[2][4], Al[2][4];               // [kf][reg]
        {
            const float* sb2 = (const float*)(smem + O_B2);
            #pragma unroll
            for (int nf = 0; nf < 4; nf++) {
                float bv0 = sb2[n0 + 8*nf + 2*t4];
                float bv1 = sb2[n0 + 8*nf + 2*t4 + 1];
                cacc[nf][0] = fmaxf(cacc[nf][0] + bv0, 0.0f);
                cacc[nf][1] = fmaxf(cacc[nf][1] + bv1, 0.0f);
                cacc[nf][2] = fmaxf(cacc[nf][2] + bv0, 0.0f);
                cacc[nf][3] = fmaxf(cacc[nf][3] + bv1, 0.0f);
            }
            #pragma unroll
            for (int kf = 0; kf < 2; kf++) {
                const float* cL = cacc[2*kf];
                const float* cH = cacc[2*kf+1];
                #pragma unroll
                for (int h = 0; h < 2; h++) {
                    float v0 = cL[2*h], v1 = cL[2*h+1];
                    float w0 = cH[2*h], w1 = cH[2*h+1];
                    uint32_t p0 = cvt2(v1, v0);
                    uint32_t p1 = cvt2(w1, w0);
                    Ah[kf][h]   = p0;
                    Ah[kf][2+h] = p1;
                    Al[kf][h]   = cvt2(v1 - __uint_as_float(p0 & 0xFFFF0000u),
                                       v0 - __uint_as_float(p0 << 16));
                    Al[kf][2+h] = cvt2(w1 - __uint_as_float(p1 & 0xFFFF0000u),
                                       w0 - __uint_as_float(p1 << 16));
                }
            }
        }

        // ---------- layer 3: partial Z[16m x 32ch] over this warp's k-slice ----------
        float zacc[4][4];
        #pragma unroll
        for (int j = 0; j < 4; j++)
            #pragma unroll
            for (int r = 0; r < 4; r++) zacc[j][r] = 0.0f;
        #pragma unroll
        for (int cp = 0; cp < 2; cp++) {           // chf pairs {0,1},{2,3}
            #pragma unroll
            for (int kf = 0; kf < 2; kf++) {
                uint32_t addrh = sb + O_W3B + (uint32_t)((cp*16 + bRow)*SA + n0 + kf*16 + bCol)*2;
                uint32_t r0,r1,r2,r3;
                LDSM4(r0,r1,r2,r3, addrh);
                uint32_t q0,q1,q2,q3;
                LDSM4(q0,q1,q2,q3, addrh + PLANE_W3);
                uint32_t bh0[2] = {r0, r1}, bl0[2] = {q0, q1};
                uint32_t bh1[2] = {r2, r3}, bl1[2] = {q2, q3};
                MMA(zacc[2*cp],   Ah[kf], bh0);
                MMA(zacc[2*cp],   Ah[kf], bl0);
                MMA(zacc[2*cp],   Al[kf], bh0);
                MMA(zacc[2*cp+1], Ah[kf], bh1);
                MMA(zacc[2*cp+1], Ah[kf], bl1);
                MMA(zacc[2*cp+1], Al[kf], bh1);
            }
        }

        // ---------- store partial Z: Zpart2[wn&1][ch][132], wn pairs merged by +=
        //            (no barrier needed before this: ZP no longer aliases A1;
        //             ordering vs pool(s-1) reads is provided by B3/B4 of set s-1
        //             and B1 of set s) ----------
        {
            // wn in {0,1} write slice wn; wn in {2,3} add into slice wn-2.
            // To avoid read-modify-write races between wn pairs, serialize with
            // a cheap strategy: slice = wn & 1; first writer (wn < 2) stores,
            // second (wn >= 2) accumulates AFTER barrier B2a.
            float* zp = (float*)(smem + O_ZP2) + (wn & 1) * 4224;
            if (wn < 2) {
                #pragma unroll
                for (int chf = 0; chf < 4; chf++) {
                    int ch = 8*chf + 2*t4;
                    int m  = m0 + g;
                    zp[ch*132 + m]         = zacc[chf][0];
                    zp[(ch+1)*132 + m]     = zacc[chf][1];
                    zp[ch*132 + m + 8]     = zacc[chf][2];
                    zp[(ch+1)*132 + m + 8] = zacc[chf][3];
                }
            }
            __syncthreads();   // B2a: first-half partials stored
            if (wn >= 2) {
                #pragma unroll
                for (int chf = 0; chf < 4; chf++) {
                    int ch = 8*chf + 2*t4;
                    int m  = m0 + g;
                    zp[ch*132 + m]         += zacc[chf][0];
                    zp[(ch+1)*132 + m]     += zacc[chf][1];
                    zp[ch*132 + m + 8]     += zacc[chf][2];
                    zp[(ch+1)*132 + m + 8] += zacc[chf][3];
                }
            }
        }
        __syncthreads();   // B3: Z partials complete

        // ---------- lane-major bitonic sorted-dot pool (1 channel per warp) ----------
        {
            const float* sb3 = (const float*)(smem + O_B3);
            const float* zp0 = (const float*)(smem + O_ZP2);
            float* sPl = (float*)(smem + O_PL);
            const int c = wid;
            const float bias = sb3[c];
            float v[4];
            {
                const float4 za = *(const float4*)(zp0 + c*132 + 4*lane);
                const float4 zb = *(const float4*)(zp0 + 4224 + c*132 + 4*lane);
                v[0] = za.x + zb.x + bias;
                v[1] = za.y + zb.y + bias;
                v[2] = za.z + zb.z + bias;
                v[3] = za.w + zb.w + bias;
            }
            #pragma unroll
            for (int k = 2; k <= 128; k <<= 1) {
                #pragma unroll
                for (int st = 64; st >= 1; st >>= 1) {
                    if (st >= k) continue;
                    if (st >= 4) {
                        const int ld = st >> 2;
                        const bool lowerLane = ((lane & ld) == 0);
                        #pragma unroll
                        for (int r = 0; r < 4; r++) {
                            float o = __shfl_xor_sync(0xffffffffu, v[r], ld);
                            bool up = (((4*lane + r) & k) == 0);
                            bool tmin = (up == lowerLane);
                            float mn = fminf(v[r], o), mx = fmaxf(v[r], o);
                            v[r] = tmin ? mn : mx;
                        }
                    } else if (st == 2) {
                        #pragma unroll
                        for (int ra = 0; ra < 2; ra++) {
                            bool up = (((4*lane + ra) & k) == 0);
                            float mn = fminf(v[ra], v[ra+2]), mx = fmaxf(v[ra], v[ra+2]);
                            v[ra]   = up ? mn : mx;
                            v[ra+2] = up ? mx : mn;
                        }
                    } else {    // st == 1
                        #pragma unroll
                        for (int ra = 0; ra < 4; ra += 2) {
                            bool up = (((4*lane + ra) & k) == 0);
                            float mn = fminf(v[ra], v[ra+1]), mx = fmaxf(v[ra], v[ra+1]);
                            v[ra]   = up ? mn : mx;
                            v[ra+1] = up ? mx : mn;
                        }
                    }
                }
            }
            // ascending idx = 4*lane + r  ->  descending rank = 127 - idx
            const float* wc = sWp + c * 128;
            const float4 w4 = *(const float4*)(wc + 124 - 4*lane);
            float sum = v[0] * w4.w + v[1] * w4.z + v[2] * w4.y + v[3] * w4.x;
            #pragma unroll
            for (int ofs = 16; ofs > 0; ofs >>= 1)
                sum += __shfl_xor_sync(0xffffffffu, sum, ofs);
            if (lane == 0) sPl[c] = sum;
        }
        __syncthreads();   // B4: sPl ready

        // ---------- reparameterize + write ----------
        if (tid < NLAT) {
            const float* sPl = (const float*)(smem + O_PL);
            float mu = sPl[2*tid];
            float lv = sPl[2*tid + 1];
            float e  = eps[(size_t)bset*NLAT + tid];
            float smp = fmaf(e, expf(0.5f * lv), mu);
            out[(size_t)bset*NLAT + tid] = mu;
            out[(size_t)(NBATCH*NLAT)   + (size_t)bset*NLAT + tid] = lv;
            out[(size_t)(2*NBATCH*NLAT) + (size_t)bset*NLAT + tid] = smp;
        }
    }
}

extern "C" void kernel_launch(void* const* d_in, const int* in_sizes, int n_in,
                              void* d_out, int out_size) {
    const float* x   = (const float*)d_in[0];
    const float* W1  = (const float*)d_in[1];
    const float* b1  = (const float*)d_in[2];
    const float* W2  = (const float*)d_in[3];
    const float* b2  = (const float*)d_in[4];
    const float* W3  = (const float*)d_in[5];
    const float* b3  = (const float*)d_in[6];
    const float* pwm = (const float*)d_in[7];
    const float* eps = (const float*)d_in[8];
    float* out = (float*)d_out;

    cudaFuncSetAttribute(enc_kernel, cudaFuncAttributeMaxDynamicSharedMemorySize, SMEM_BYTES);
    enc_kernel<<<GRID, TPB, SMEM_BYTES>>>(x, W1, b1, W2, b2, W3, b3, pwm, eps, out);
}